// round 5
// baseline (speedup 1.0000x reference)
#include <cuda_runtime.h>
#include <math.h>

#define NN 50000          // N_NODES == M_NODES
#define KNBR 32
#define F 128
#define WSIZE 3

typedef unsigned long long ull;

// Scratch (device globals: allocation-free per harness rules)
__device__ float  g_h[(size_t)NN * F];     // h = input @ W  (fp32)
__device__ double g_hc1[NN];               // h . c1 (fp64 accumulation ~ truth)
__device__ double g_hc2[NN];               // h . c2
__device__ ull    g_Wp[64 * F];            // W pre-packed: (W[2kp][c], W[2kp+1][c])

// ---- packed f32x2 helpers ----
static __device__ __forceinline__ ull pack2(float lo, float hi) {
    ull r;
    asm("mov.b64 %0, {%1, %2};" : "=l"(r) : "f"(lo), "f"(hi));
    return r;
}
static __device__ __forceinline__ void unpack2(ull v, float& lo, float& hi) {
    asm("mov.b64 {%0, %1}, %2;" : "=f"(lo), "=f"(hi) : "l"(v));
}
static __device__ __forceinline__ void ffma2(ull& d, ull a, ull b) {
    asm("fma.rn.f32x2 %0, %1, %2, %0;" : "+l"(d) : "l"(a), "l"(b));
}

// ============================================================================
// Kernel 0: pre-pack W into even/odd-k f32x2 pairs (once; tiny)
// g_Wp[kp*128 + c] = (W[2kp][c], W[2kp+1][c])
// ============================================================================
__global__ void pack_w_kernel(const float* __restrict__ W)
{
    const int i = blockIdx.x * blockDim.x + threadIdx.x;   // 0..8191
    const int kp  = i >> 7;
    const int col = i & 127;
    g_Wp[i] = pack2(W[(2 * kp) * F + col], W[(2 * kp + 1) * F + col]);
}

// ============================================================================
// Kernel A: h = input @ W (fp32, f32x2 FMA), fused hc1/hc2 dot products in FP64
// block = 128 threads, 16 rows/block. Each warp: 4 rows; each lane: 4 cols.
// Accumulation order identical to round-4 kernel (acc.lo = even k in order,
// acc.hi = odd k in order, final lo+hi) -> bitwise-identical h.
// ============================================================================
__global__ void __launch_bounds__(128) gemm_hc_kernel(
    const float* __restrict__ inp,
    const float* __restrict__ c1,
    const float* __restrict__ c2)
{
    __shared__ float s_in[16][F];

    const int tid  = threadIdx.x;
    const int lane = tid & 31;
    const int warp = tid >> 5;
    const int row0 = blockIdx.x * 16;

    // stage 16 input rows (2048 floats) into shared
    {
        const float4* gin  = (const float4*)(inp + (size_t)row0 * F);
        float4*       sin4 = (float4*)&s_in[0][0];
        #pragma unroll
        for (int i = 0; i < 4; i++)
            sin4[tid + i * 128] = gin[tid + i * 128];
    }
    __syncthreads();

    ull acc[4][4];
    #pragma unroll
    for (int r = 0; r < 4; r++)
        #pragma unroll
        for (int i = 0; i < 4; i++)
            acc[r][i] = 0ULL;

    const int colbase = lane * 4;
    const int rbase   = warp * 4;

    #pragma unroll 8
    for (int kp2 = 0; kp2 < 32; kp2++) {       // k = 4*kp2 .. 4*kp2+3
        const int kpA = 2 * kp2, kpB = 2 * kp2 + 1;
        const ulonglong2 wA0 = *(const ulonglong2*)(g_Wp + kpA * F + colbase);
        const ulonglong2 wA1 = *(const ulonglong2*)(g_Wp + kpA * F + colbase + 2);
        const ulonglong2 wB0 = *(const ulonglong2*)(g_Wp + kpB * F + colbase);
        const ulonglong2 wB1 = *(const ulonglong2*)(g_Wp + kpB * F + colbase + 2);
        #pragma unroll
        for (int r = 0; r < 4; r++) {
            const float4 iv = *(const float4*)&s_in[rbase + r][kp2 * 4];
            const ull ipA = pack2(iv.x, iv.y);   // k, k+1
            const ull ipB = pack2(iv.z, iv.w);   // k+2, k+3
            ffma2(acc[r][0], ipA, wA0.x);
            ffma2(acc[r][1], ipA, wA0.y);
            ffma2(acc[r][2], ipA, wA1.x);
            ffma2(acc[r][3], ipA, wA1.y);
            ffma2(acc[r][0], ipB, wB0.x);
            ffma2(acc[r][1], ipB, wB0.y);
            ffma2(acc[r][2], ipB, wB1.x);
            ffma2(acc[r][3], ipB, wB1.y);
        }
    }

    const float4 cv1 = *(const float4*)(c1 + colbase);
    const float4 cv2 = *(const float4*)(c2 + colbase);

    #pragma unroll
    for (int r = 0; r < 4; r++) {
        float4 hv;
        float lo, hi;
        unpack2(acc[r][0], lo, hi); hv.x = lo + hi;
        unpack2(acc[r][1], lo, hi); hv.y = lo + hi;
        unpack2(acc[r][2], lo, hi); hv.z = lo + hi;
        unpack2(acc[r][3], lo, hi); hv.w = lo + hi;

        const int row = row0 + rbase + r;
        *(float4*)(g_h + (size_t)row * F + colbase) = hv;

        // hc dot products in FP64 (so fp32-rounded value == ref's +-1 ulp)
        double d1 = (double)hv.x * (double)cv1.x + (double)hv.y * (double)cv1.y
                  + (double)hv.z * (double)cv1.z + (double)hv.w * (double)cv1.w;
        double d2 = (double)hv.x * (double)cv2.x + (double)hv.y * (double)cv2.y
                  + (double)hv.z * (double)cv2.z + (double)hv.w * (double)cv2.w;
        #pragma unroll
        for (int off = 16; off > 0; off >>= 1) {
            d1 += __shfl_down_sync(0xffffffffu, d1, off);
            d2 += __shfl_down_sync(0xffffffffu, d2, off);
        }
        if (lane == 0) {
            g_hc1[row] = d1;
            g_hc2[row] = d2;
        }
    }
}

// ============================================================================
// Kernel B: per-node attention (one warp per node; lane j = neighbor j).
// Decision chain emulates the reference fp32 arithmetic bit-faithfully.
// Sequential sum / prefix-sum broadcasts now go through shared memory with
// LDS.128 (4 values per load) instead of 32 SHFLs per pass; running-sum with
// capture-at-index reproduces EXACTLY the same fp32 add sequence as round 4.
// ============================================================================
__global__ void __launch_bounds__(256) attn_kernel(
    const int* __restrict__ adj,
    const int* __restrict__ deg,
    float* __restrict__ out)
{
    __shared__ float s_buf[8][KNBR];

    const unsigned FULL = 0xffffffffu;
    const int warp = threadIdx.x >> 5;
    const int lane = threadIdx.x & 31;
    const int m    = blockIdx.x * 8 + warp;   // 6250 * 8 == 50000 exactly

    const int  d     = deg[m];
    const int  a     = adj[(size_t)m * KNBR + lane];
    const bool valid = (lane < d);

    const float NEG_INF = __int_as_float(0xff800000u);

    // e in fp32, formed from fp64-accurate hc values (== ref's fp32 e +-1 ulp)
    float e32 = NEG_INF;
    if (valid) {
        const float x = (float)(g_hc1[m] + g_hc2[a]);
        e32 = (x >= 0.f) ? x : 0.2f * x;
    }

    // max (exact, order-independent)
    float mx = e32;
    #pragma unroll
    for (int off = 16; off > 0; off >>= 1)
        mx = fmaxf(mx, __shfl_xor_sync(FULL, mx, off));

    // exp: fp64 exp of the fp32 argument, rounded -> ~correctly-rounded expf
    const float p = valid ? (float)exp((double)(e32 - mx)) : 0.f;

    // ---- pass 1: sequential fp32 sum of p (same order as ref reduce) ----
    s_buf[warp][lane] = p;
    __syncwarp();
    float s = 0.f;
    #pragma unroll
    for (int q = 0; q < 8; q++) {
        const float4 v = *(const float4*)&s_buf[warp][q * 4];
        s += v.x; s += v.y; s += v.z; s += v.w;
    }

    const float att = p / s;   // fp32 divide, as reference

    // ---- pass 2: sequential fp32 prefix sum with capture-at-index ----
    __syncwarp();
    s_buf[warp][lane] = att;
    __syncwarp();
    float run = 0.f, csum = 0.f, shifted = 0.f;
    const int lm3 = lane - WSIZE;
    #pragma unroll
    for (int q = 0; q < 8; q++) {
        const float4 v = *(const float4*)&s_buf[warp][q * 4];
        const int k0 = q * 4;
        run += v.x; if (k0 + 0 == lane) csum = run; if (k0 + 0 == lm3) shifted = run;
        run += v.y; if (k0 + 1 == lane) csum = run; if (k0 + 1 == lm3) shifted = run;
        run += v.z; if (k0 + 2 == lane) csum = run; if (k0 + 2 == lm3) shifted = run;
        run += v.w; if (k0 + 3 == lane) csum = run; if (k0 + 3 == lm3) shifted = run;
    }

    // win = csum - csum_shifted_by_3  (fp32, same cancellation as reference)
    // shifted == 0 for lane < 3, matching the reference's zero-padding.
    float win = -1.0f;
    if (lane >= WSIZE - 1 && lane < d)
        win = csum - shifted;

    // argmax, first occurrence on ties (np.argmax semantics)
    float bw = win;
    int   bj = lane;
    #pragma unroll
    for (int off = 16; off > 0; off >>= 1) {
        const float ow = __shfl_down_sync(FULL, bw, off);
        const int   oj = __shfl_down_sync(FULL, bj, off);
        if (ow > bw || (ow == bw && oj < bj)) { bw = ow; bj = oj; }
    }
    const int jstar = __shfl_sync(FULL, bj, 0);   // jstar >= 2 always (deg >= 3)

    const float scale = (float)d / 3.0f;
    const float t = (lane >= jstar - (WSIZE - 1) && lane <= jstar) ? att * scale : 0.f;

    // broadcast the 3 surviving (neighbor, weight) pairs (ascending k order)
    const float w0 = __shfl_sync(FULL, t, jstar - 2);
    const float w1 = __shfl_sync(FULL, t, jstar - 1);
    const float w2 = __shfl_sync(FULL, t, jstar);
    const int   a0 = __shfl_sync(FULL, a, jstar - 2);
    const int   a1 = __shfl_sync(FULL, a, jstar - 1);
    const int   a2 = __shfl_sync(FULL, a, jstar);

    // gather 3 h rows (512 B each, L2-resident), fp32 FMA chain, elu
    const float4 v0 = ((const float4*)(g_h + (size_t)a0 * F))[lane];
    const float4 v1 = ((const float4*)(g_h + (size_t)a1 * F))[lane];
    const float4 v2 = ((const float4*)(g_h + (size_t)a2 * F))[lane];

    float4 o;
    o.x = fmaf(w2, v2.x, fmaf(w1, v1.x, w0 * v0.x));
    o.y = fmaf(w2, v2.y, fmaf(w1, v1.y, w0 * v0.y));
    o.z = fmaf(w2, v2.z, fmaf(w1, v1.z, w0 * v0.z));
    o.w = fmaf(w2, v2.w, fmaf(w1, v1.w, w0 * v0.w));

    o.x = (o.x > 0.f) ? o.x : expm1f(o.x);
    o.y = (o.y > 0.f) ? o.y : expm1f(o.y);
    o.z = (o.z > 0.f) ? o.z : expm1f(o.z);
    o.w = (o.w > 0.f) ? o.w : expm1f(o.w);

    ((float4*)out)[(size_t)m * (F / 4) + lane] = o;
}

extern "C" void kernel_launch(void* const* d_in, const int* in_sizes, int n_in,
                              void* d_out, int out_size) {
    const float* inp = (const float*)d_in[0];
    const float* W   = (const float*)d_in[1];
    const float* c1  = (const float*)d_in[2];
    const float* c2  = (const float*)d_in[3];
    const int*   adj = (const int*)d_in[4];
    const int*   deg = (const int*)d_in[5];
    float*       out = (float*)d_out;

    pack_w_kernel<<<32, 256>>>(W);                      // 8192 threads
    gemm_hc_kernel<<<NN / 16, 128>>>(inp, c1, c2);      // 3125 blocks
    attn_kernel<<<NN / 8, 256>>>(adj, deg, out);        // 6250 blocks
}

// round 6
// speedup vs baseline: 1.2618x; 1.2618x over previous
#include <cuda_runtime.h>
#include <math.h>

#define NN 50000          // N_NODES == M_NODES
#define KNBR 32
#define F 128
#define WSIZE 3

typedef unsigned long long ull;

// Scratch (device globals: allocation-free per harness rules)
__device__ float g_h[(size_t)NN * F];     // h = input @ W  (fp32)
__device__ float g_hc1[NN];               // fl32( fp64-accurate h . c1 )
__device__ float g_hc2[NN];               // fl32( fp64-accurate h . c2 )

// ---- packed f32x2 helpers ----
static __device__ __forceinline__ ull pack2(float lo, float hi) {
    ull r;
    asm("mov.b64 %0, {%1, %2};" : "=l"(r) : "f"(lo), "f"(hi));
    return r;
}
static __device__ __forceinline__ void unpack2(ull v, float& lo, float& hi) {
    asm("mov.b64 {%0, %1}, %2;" : "=f"(lo), "=f"(hi) : "l"(v));
}
static __device__ __forceinline__ void ffma2(ull& d, ull a, ull b) {
    asm("fma.rn.f32x2 %0, %1, %2, %0;" : "+l"(d) : "l"(a), "l"(b));
}

// ============================================================================
// Kernel A: h = input @ W (fp32, f32x2 FMA), fused hc1/hc2 dot products in FP64
// block = 128 threads, 16 rows/block. Each warp: 4 rows; each lane: 4 cols.
// ============================================================================
__global__ void __launch_bounds__(128) gemm_hc_kernel(
    const float* __restrict__ inp,
    const float* __restrict__ W,
    const float* __restrict__ c1,
    const float* __restrict__ c2)
{
    __shared__ float s_in[16][F];

    const int tid  = threadIdx.x;
    const int lane = tid & 31;
    const int warp = tid >> 5;
    const int row0 = blockIdx.x * 16;

    // stage 16 input rows (2048 floats) into shared
    {
        const float4* gin  = (const float4*)(inp + (size_t)row0 * F);
        float4*       sin4 = (float4*)&s_in[0][0];
        #pragma unroll
        for (int i = 0; i < 4; i++)
            sin4[tid + i * 128] = gin[tid + i * 128];
    }
    __syncthreads();

    ull acc[4][4];
    #pragma unroll
    for (int r = 0; r < 4; r++)
        #pragma unroll
        for (int i = 0; i < 4; i++)
            acc[r][i] = 0ULL;

    const int colbase = lane * 4;
    const int rbase   = warp * 4;

    #pragma unroll 8
    for (int k = 0; k < F; k += 2) {
        const float4 wa = *(const float4*)(W + (size_t)k * F + colbase);
        const float4 wb = *(const float4*)(W + (size_t)(k + 1) * F + colbase);
        const ull wp0 = pack2(wa.x, wb.x);
        const ull wp1 = pack2(wa.y, wb.y);
        const ull wp2 = pack2(wa.z, wb.z);
        const ull wp3 = pack2(wa.w, wb.w);
        #pragma unroll
        for (int r = 0; r < 4; r++) {
            const float2 in2 = *(const float2*)&s_in[rbase + r][k];
            const ull ip = pack2(in2.x, in2.y);
            ffma2(acc[r][0], ip, wp0);
            ffma2(acc[r][1], ip, wp1);
            ffma2(acc[r][2], ip, wp2);
            ffma2(acc[r][3], ip, wp3);
        }
    }

    const float4 cv1 = *(const float4*)(c1 + colbase);
    const float4 cv2 = *(const float4*)(c2 + colbase);

    #pragma unroll
    for (int r = 0; r < 4; r++) {
        float4 hv;
        float lo, hi;
        unpack2(acc[r][0], lo, hi); hv.x = lo + hi;
        unpack2(acc[r][1], lo, hi); hv.y = lo + hi;
        unpack2(acc[r][2], lo, hi); hv.z = lo + hi;
        unpack2(acc[r][3], lo, hi); hv.w = lo + hi;

        const int row = row0 + rbase + r;
        *(float4*)(g_h + (size_t)row * F + colbase) = hv;

        // hc dot products in FP64 (accurate), stored as fp32 (= ref's fp32
        // e_self / per-neighbor e_nbr values to within ~0.5 ulp)
        double d1 = (double)hv.x * (double)cv1.x + (double)hv.y * (double)cv1.y
                  + (double)hv.z * (double)cv1.z + (double)hv.w * (double)cv1.w;
        double d2 = (double)hv.x * (double)cv2.x + (double)hv.y * (double)cv2.y
                  + (double)hv.z * (double)cv2.z + (double)hv.w * (double)cv2.w;
        #pragma unroll
        for (int off = 16; off > 0; off >>= 1) {
            d1 += __shfl_down_sync(0xffffffffu, d1, off);
            d2 += __shfl_down_sync(0xffffffffu, d2, off);
        }
        if (lane == 0) {
            g_hc1[row] = (float)d1;
            g_hc2[row] = (float)d2;
        }
    }
}

// ============================================================================
// Kernel B: per-node attention (one warp per node; lane j = neighbor j).
// Decision chain emulates the reference fp32 arithmetic:
//   e = leaky(fp32 hc1 + fp32 hc2)  [fp32 add, same form as ref]
//   expf (ulp-level match to ref's exp) -> SEQUENTIAL fp32 sum -> fp32 div ->
//   SEQUENTIAL fp32 prefix sum -> fp32 win = csum - shifted -> first-max argmax.
// ============================================================================
__global__ void __launch_bounds__(256) attn_kernel(
    const int* __restrict__ adj,
    const int* __restrict__ deg,
    float* __restrict__ out)
{
    __shared__ float s_buf[8][KNBR];

    const unsigned FULL = 0xffffffffu;
    const int warp = threadIdx.x >> 5;
    const int lane = threadIdx.x & 31;
    const int m    = blockIdx.x * 8 + warp;   // 6250 * 8 == 50000 exactly

    const int  d     = deg[m];
    const int  a     = adj[(size_t)m * KNBR + lane];
    const bool valid = (lane < d);

    const float NEG_INF = __int_as_float(0xff800000u);

    float e32 = NEG_INF;
    if (valid) {
        const float x = g_hc1[m] + g_hc2[a];   // fp32 add, as reference
        e32 = (x >= 0.f) ? x : 0.2f * x;
    }

    // max (exact, order-independent)
    float mx = e32;
    #pragma unroll
    for (int off = 16; off > 0; off >>= 1)
        mx = fmaxf(mx, __shfl_xor_sync(FULL, mx, off));

    // expf: libdevice exp, ulp-level match to the reference's exp
    const float p = valid ? expf(e32 - mx) : 0.f;

    // ---- pass 1: sequential fp32 sum of p (same order as ref reduce) ----
    s_buf[warp][lane] = p;
    __syncwarp();
    float s = 0.f;
    #pragma unroll
    for (int q = 0; q < 8; q++) {
        const float4 v = *(const float4*)&s_buf[warp][q * 4];
        s += v.x; s += v.y; s += v.z; s += v.w;
    }

    const float att = p / s;   // fp32 divide, as reference

    // ---- pass 2: sequential fp32 prefix sum with capture-at-index ----
    __syncwarp();
    s_buf[warp][lane] = att;
    __syncwarp();
    float run = 0.f, csum = 0.f, shifted = 0.f;
    const int lm3 = lane - WSIZE;
    #pragma unroll
    for (int q = 0; q < 8; q++) {
        const float4 v = *(const float4*)&s_buf[warp][q * 4];
        const int k0 = q * 4;
        run += v.x; if (k0 + 0 == lane) csum = run; if (k0 + 0 == lm3) shifted = run;
        run += v.y; if (k0 + 1 == lane) csum = run; if (k0 + 1 == lm3) shifted = run;
        run += v.z; if (k0 + 2 == lane) csum = run; if (k0 + 2 == lm3) shifted = run;
        run += v.w; if (k0 + 3 == lane) csum = run; if (k0 + 3 == lm3) shifted = run;
    }

    // win = csum - csum_shifted_by_3 (fp32, same cancellation as reference);
    // shifted == 0 for lane < 3, matching the reference's zero-padding.
    float win = -1.0f;
    if (lane >= WSIZE - 1 && lane < d)
        win = csum - shifted;

    // argmax, first occurrence on ties (np.argmax semantics)
    float bw = win;
    int   bj = lane;
    #pragma unroll
    for (int off = 16; off > 0; off >>= 1) {
        const float ow = __shfl_down_sync(FULL, bw, off);
        const int   oj = __shfl_down_sync(FULL, bj, off);
        if (ow > bw || (ow == bw && oj < bj)) { bw = ow; bj = oj; }
    }
    const int jstar = __shfl_sync(FULL, bj, 0);   // jstar >= 2 always (deg >= 3)

    const float scale = (float)d / 3.0f;
    const float t = (lane >= jstar - (WSIZE - 1) && lane <= jstar) ? att * scale : 0.f;

    // broadcast the 3 surviving (neighbor, weight) pairs (ascending k order)
    const float w0 = __shfl_sync(FULL, t, jstar - 2);
    const float w1 = __shfl_sync(FULL, t, jstar - 1);
    const float w2 = __shfl_sync(FULL, t, jstar);
    const int   a0 = __shfl_sync(FULL, a, jstar - 2);
    const int   a1 = __shfl_sync(FULL, a, jstar - 1);
    const int   a2 = __shfl_sync(FULL, a, jstar);

    // gather 3 h rows (512 B each, L2-resident), fp32 FMA chain, elu
    const float4 v0 = ((const float4*)(g_h + (size_t)a0 * F))[lane];
    const float4 v1 = ((const float4*)(g_h + (size_t)a1 * F))[lane];
    const float4 v2 = ((const float4*)(g_h + (size_t)a2 * F))[lane];

    float4 o;
    o.x = fmaf(w2, v2.x, fmaf(w1, v1.x, w0 * v0.x));
    o.y = fmaf(w2, v2.y, fmaf(w1, v1.y, w0 * v0.y));
    o.z = fmaf(w2, v2.z, fmaf(w1, v1.z, w0 * v0.z));
    o.w = fmaf(w2, v2.w, fmaf(w1, v1.w, w0 * v0.w));

    o.x = (o.x > 0.f) ? o.x : expm1f(o.x);
    o.y = (o.y > 0.f) ? o.y : expm1f(o.y);
    o.z = (o.z > 0.f) ? o.z : expm1f(o.z);
    o.w = (o.w > 0.f) ? o.w : expm1f(o.w);

    ((float4*)out)[(size_t)m * (F / 4) + lane] = o;
}

extern "C" void kernel_launch(void* const* d_in, const int* in_sizes, int n_in,
                              void* d_out, int out_size) {
    const float* inp = (const float*)d_in[0];
    const float* W   = (const float*)d_in[1];
    const float* c1  = (const float*)d_in[2];
    const float* c2  = (const float*)d_in[3];
    const int*   adj = (const int*)d_in[4];
    const int*   deg = (const int*)d_in[5];
    float*       out = (float*)d_out;

    gemm_hc_kernel<<<NN / 16, 128>>>(inp, W, c1, c2);   // 3125 blocks
    attn_kernel<<<NN / 8, 256>>>(adj, deg, out);        // 6250 blocks
}